// round 14
// baseline (speedup 1.0000x reference)
#include <cuda_runtime.h>
#include <cuda_fp16.h>
#include <cstdint>

#define MAX_NODES 100000
#define D 128
#define EPT 7           // edges per thread (edge kernel)
#define EBLK 1024       // threads per block (edge kernel)

#define TABLE_BYTES (MAX_NODES * 2)      // one fp16 table = 200000 B
#define SMEM_TABLE_OFF 16                // mbarrier at 0, table at 16
#define SMEM_TOTAL (SMEM_TABLE_OFF + TABLE_BYTES)

// Per-node projections, both fp16. Bias folded into d at the node pass.
__device__ __align__(16) __half g_s_h[MAX_NODES];
__device__ __align__(16) __half g_d_h[MAX_NODES];

__device__ __forceinline__ uint32_t smem_u32(const void* p) {
    uint32_t a;
    asm("{ .reg .u64 t; cvta.to.shared.u64 t, %1; cvt.u32.u64 %0, t; }" : "=r"(a) : "l"(p));
    return a;
}

__device__ __forceinline__ float sigmoidf_fast(float z) {
    return 1.0f / (1.0f + __expf(-z));
}

// Kernel 1 (unchanged, measured ~7.3us): 8 nodes per warp via 8-lane
// subgroups, 2 nodes per thread, all 8 LDG.128 up-front (MLP=8).
__global__ void node_dots_kernel(const float4* __restrict__ x4,
                                 const float* __restrict__ W,
                                 const float* __restrict__ b,
                                 int n_nodes) {
    __shared__ float4 ws4[32];
    __shared__ float4 wd4[32];
    int tid = threadIdx.x;
    if (tid < 32) ws4[tid] = ((const float4*)W)[tid];
    else if (tid < 64) wd4[tid - 32] = ((const float4*)W)[tid - 32 + 32];
    __syncthreads();

    int lane = tid & 31;
    int g    = lane & 7;
    int sub  = lane >> 3;
    int warpId = (blockIdx.x * blockDim.x + tid) >> 5;
    int base = warpId * 8;
    int nodeA = base + sub;
    int nodeB = base + 4 + sub;
    if (nodeA >= n_nodes) return;
    bool hasB = nodeB < n_nodes;

    const float4* rowA = x4 + (size_t)nodeA * 32;
    const float4* rowB = x4 + (size_t)nodeB * 32;

    float4 va[4], vb[4];
    #pragma unroll
    for (int it = 0; it < 4; it++) va[it] = rowA[it * 8 + g];
    #pragma unroll
    for (int it = 0; it < 4; it++)
        vb[it] = hasB ? rowB[it * 8 + g] : make_float4(0.f, 0.f, 0.f, 0.f);

    float sA = 0.f, dA = 0.f, sB = 0.f, dB = 0.f;
    #pragma unroll
    for (int it = 0; it < 4; it++) {
        float4 a = ws4[it * 8 + g];
        float4 c = wd4[it * 8 + g];
        sA += va[it].x * a.x + va[it].y * a.y + va[it].z * a.z + va[it].w * a.w;
        dA += va[it].x * c.x + va[it].y * c.y + va[it].z * c.z + va[it].w * c.w;
        sB += vb[it].x * a.x + vb[it].y * a.y + vb[it].z * a.z + vb[it].w * a.w;
        dB += vb[it].x * c.x + vb[it].y * c.y + vb[it].z * c.z + vb[it].w * c.w;
    }
    #pragma unroll
    for (int off = 4; off > 0; off >>= 1) {
        sA += __shfl_down_sync(0xFFFFFFFFu, sA, off);
        dA += __shfl_down_sync(0xFFFFFFFFu, dA, off);
        sB += __shfl_down_sync(0xFFFFFFFFu, sB, off);
        dB += __shfl_down_sync(0xFFFFFFFFu, dB, off);
    }
    if (g == 0) {
        float b0 = __ldg(b);
        g_s_h[nodeA] = __float2half(sA);
        g_d_h[nodeA] = __float2half(dA + b0);
        if (hasB) {
            g_s_h[nodeB] = __float2half(sB);
            g_d_h[nodeB] = __float2half(dB + b0);
        }
    }
}

// Kernel 2: HYBRID gather. s-table broadcast once into smem by TMA (async
// proxy); d-gathers go through L1tex (fp16 d-table = 200KB, L1-resident)
// and are issued in phase A so their wavefront drain overlaps the broadcast.
// Both gather engines (smem crossbar + L1tex) work concurrently; the second
// broadcast and its dead window are gone.
__global__ void __launch_bounds__(EBLK, 1)
edge_score_hybrid_kernel(const int* __restrict__ src,
                         const int* __restrict__ dst,
                         float* __restrict__ out,
                         int n_edges) {
    extern __shared__ char smem_raw[];
    __half* tab = reinterpret_cast<__half*>(smem_raw + SMEM_TABLE_OFF);
    uint32_t mbar = smem_u32(smem_raw);
    uint32_t tab_a = smem_u32(tab);

    int tid = threadIdx.x;

    if (tid == 0) {
        asm volatile("mbarrier.init.shared.b64 [%0], 1;" :: "r"(mbar) : "memory");
    }
    __syncthreads();
    // Broadcast: s-table only.
    if (tid == 0) {
        asm volatile("mbarrier.arrive.expect_tx.shared.b64 _, [%0], %1;"
                     :: "r"(mbar), "r"((uint32_t)TABLE_BYTES) : "memory");
        asm volatile(
            "cp.async.bulk.shared::cta.global.mbarrier::complete_tx::bytes [%0], [%1], %2, [%3];"
            :: "r"(tab_a), "l"((const void*)g_s_h),
               "r"((uint32_t)TABLE_BYTES), "r"(mbar) : "memory");
    }

    int gtid = blockIdx.x * EBLK + tid;
    int stride = gridDim.x * EBLK;

    // Phase A: index loads + fp16 d-gathers via L1tex, all in flight while
    // the broadcast flies.
    int    si[EPT];
    __half dh[EPT];
    #pragma unroll
    for (int k = 0; k < EPT; k++) {
        int e = gtid + k * stride;
        bool ok = e < n_edges;
        si[k]  = ok ? __ldcs(src + e) : 0;
        int di = ok ? __ldcs(dst + e) : 0;
        dh[k]  = g_d_h[di];
    }

    // Wait for the s-table (acquire orders the LDS reads below).
    asm volatile(
        "{\n\t.reg .pred P;\n\t"
        "W0_%=:\n\t"
        "mbarrier.try_wait.parity.acquire.cta.shared::cta.b64 P, [%0], 0, 0x989680;\n\t"
        "@!P bra W0_%=;\n\t}"
        :: "r"(mbar) : "memory");

    // Phase B: LDS s-gathers + add + sigmoid + coalesced stores.
    #pragma unroll
    for (int k = 0; k < EPT; k++) {
        int e = gtid + k * stride;
        if (e < n_edges) {
            float logit = __half2float(tab[si[k]]) + __half2float(dh[k]);
            __stcs(out + e, sigmoidf_fast(logit));
        }
    }
}

extern "C" void kernel_launch(void* const* d_in, const int* in_sizes, int n_in,
                              void* d_out, int out_size) {
    const float* x   = (const float*)d_in[0];
    const int*   src = (const int*)d_in[1];
    const int*   dst = (const int*)d_in[2];
    const float* W   = (const float*)d_in[3];
    const float* b   = (const float*)d_in[4];
    float*       out = (float*)d_out;

    int n_nodes = in_sizes[0] / D;
    int n_edges = in_sizes[1];

    // Kernel 1: 8 nodes per warp, 8 warps/block -> 64 nodes/block
    {
        int nodes_per_block = 8 * 8;
        int blocks = (n_nodes + nodes_per_block - 1) / nodes_per_block;
        node_dots_kernel<<<blocks, 256>>>((const float4*)x, W, b, n_nodes);
    }
    // Kernel 2: hybrid LDS/L1tex edge scoring (grid ~140, single wave)
    {
        static bool attr_set = false;
        if (!attr_set) {
            cudaFuncSetAttribute(edge_score_hybrid_kernel,
                                 cudaFuncAttributeMaxDynamicSharedMemorySize,
                                 SMEM_TOTAL);
            attr_set = true;
        }
        long long per_blk = (long long)EBLK * EPT;
        int blocks = (int)((n_edges + per_blk - 1) / per_blk);  // 140 for 1e6
        edge_score_hybrid_kernel<<<blocks, EBLK, SMEM_TOTAL>>>(src, dst, out, n_edges);
    }
}

// round 15
// speedup vs baseline: 1.2393x; 1.2393x over previous
#include <cuda_runtime.h>
#include <cuda_fp16.h>
#include <cstdint>

#define MAX_NODES 100000
#define HALF_NODES (MAX_NODES / 2)
#define D 128
#define EPT 7           // edges per thread (edge kernel)
#define EBLK 1024       // threads per block (edge kernel)

#define TABLE_BYTES (MAX_NODES * 2)      // one fp16 table = 200000 B
#define HALF_BYTES  (TABLE_BYTES / 2)    // 100000 B (16B-multiple)
#define SMEM_TABLE_OFF 16                // mbar0 @0, mbar1 @8, table @16
#define SMEM_TOTAL (SMEM_TABLE_OFF + TABLE_BYTES)

// Per-node projections, both fp16. Bias folded into d at the node pass.
__device__ __align__(16) __half g_s_h[MAX_NODES];
__device__ __align__(16) __half g_d_h[MAX_NODES];

__device__ __forceinline__ uint32_t smem_u32(const void* p) {
    uint32_t a;
    asm("{ .reg .u64 t; cvta.to.shared.u64 t, %1; cvt.u32.u64 %0, t; }" : "=r"(a) : "l"(p));
    return a;
}

__device__ __forceinline__ float sigmoidf_fast(float z) {
    return 1.0f / (1.0f + __expf(-z));
}

__device__ __forceinline__ void mbar_wait(uint32_t mbar, int parity) {
    asm volatile(
        "{\n\t.reg .pred P;\n\t"
        "W_%=:\n\t"
        "mbarrier.try_wait.parity.acquire.cta.shared::cta.b64 P, [%0], %1, 0x989680;\n\t"
        "@!P bra W_%=;\n\t}"
        :: "r"(mbar), "r"(parity) : "memory");
}

__device__ __forceinline__ void bulk_copy(uint32_t smem_dst, const void* gsrc,
                                          uint32_t bytes, uint32_t mbar) {
    asm volatile("mbarrier.arrive.expect_tx.shared.b64 _, [%0], %1;"
                 :: "r"(mbar), "r"(bytes) : "memory");
    asm volatile(
        "cp.async.bulk.shared::cta.global.mbarrier::complete_tx::bytes [%0], [%1], %2, [%3];"
        :: "r"(smem_dst), "l"(gsrc), "r"(bytes), "r"(mbar) : "memory");
}

// Kernel 1 (unchanged, ~7.3us): 8 nodes per warp via 8-lane subgroups,
// 2 nodes per thread, all 8 LDG.128 up-front (MLP=8).
__global__ void node_dots_kernel(const float4* __restrict__ x4,
                                 const float* __restrict__ W,
                                 const float* __restrict__ b,
                                 int n_nodes) {
    __shared__ float4 ws4[32];
    __shared__ float4 wd4[32];
    int tid = threadIdx.x;
    if (tid < 32) ws4[tid] = ((const float4*)W)[tid];
    else if (tid < 64) wd4[tid - 32] = ((const float4*)W)[tid - 32 + 32];
    __syncthreads();

    int lane = tid & 31;
    int g    = lane & 7;
    int sub  = lane >> 3;
    int warpId = (blockIdx.x * blockDim.x + tid) >> 5;
    int base = warpId * 8;
    int nodeA = base + sub;
    int nodeB = base + 4 + sub;
    if (nodeA >= n_nodes) return;
    bool hasB = nodeB < n_nodes;

    const float4* rowA = x4 + (size_t)nodeA * 32;
    const float4* rowB = x4 + (size_t)nodeB * 32;

    float4 va[4], vb[4];
    #pragma unroll
    for (int it = 0; it < 4; it++) va[it] = rowA[it * 8 + g];
    #pragma unroll
    for (int it = 0; it < 4; it++)
        vb[it] = hasB ? rowB[it * 8 + g] : make_float4(0.f, 0.f, 0.f, 0.f);

    float sA = 0.f, dA = 0.f, sB = 0.f, dB = 0.f;
    #pragma unroll
    for (int it = 0; it < 4; it++) {
        float4 a = ws4[it * 8 + g];
        float4 c = wd4[it * 8 + g];
        sA += va[it].x * a.x + va[it].y * a.y + va[it].z * a.z + va[it].w * a.w;
        dA += va[it].x * c.x + va[it].y * c.y + va[it].z * c.z + va[it].w * c.w;
        sB += vb[it].x * a.x + vb[it].y * a.y + vb[it].z * a.z + vb[it].w * a.w;
        dB += vb[it].x * c.x + vb[it].y * c.y + vb[it].z * c.z + vb[it].w * c.w;
    }
    #pragma unroll
    for (int off = 4; off > 0; off >>= 1) {
        sA += __shfl_down_sync(0xFFFFFFFFu, sA, off);
        dA += __shfl_down_sync(0xFFFFFFFFu, dA, off);
        sB += __shfl_down_sync(0xFFFFFFFFu, sB, off);
        dB += __shfl_down_sync(0xFFFFFFFFu, dB, off);
    }
    if (g == 0) {
        float b0 = __ldg(b);
        g_s_h[nodeA] = __float2half(sA);
        g_d_h[nodeA] = __float2half(dA + b0);
        if (hasB) {
            g_s_h[nodeB] = __float2half(sB);
            g_d_h[nodeB] = __float2half(dB + b0);
        }
    }
}

// Kernel 2: PIPELINED table-swap. Each table broadcast as two concurrent
// 100KB halves on two mbarriers into one contiguous 200KB buffer (gather
// addressing unchanged). s_lo gathers overlap the s_hi copy; d_lo compute+
// stores overlap the d_hi copy. Removes most of the bc2 dead window.
__global__ void __launch_bounds__(EBLK, 1)
edge_score_swap_kernel(const int* __restrict__ src,
                       const int* __restrict__ dst,
                       float* __restrict__ out,
                       int n_edges) {
    extern __shared__ char smem_raw[];
    __half* tab = reinterpret_cast<__half*>(smem_raw + SMEM_TABLE_OFF);
    uint32_t mbar0 = smem_u32(smem_raw);
    uint32_t mbar1 = mbar0 + 8;
    uint32_t tab_a = smem_u32(tab);

    int tid = threadIdx.x;

    if (tid == 0) {
        asm volatile("mbarrier.init.shared.b64 [%0], 1;" :: "r"(mbar0) : "memory");
        asm volatile("mbarrier.init.shared.b64 [%0], 1;" :: "r"(mbar1) : "memory");
    }
    __syncthreads();
    // Broadcast s-table as two concurrent halves.
    if (tid == 0) {
        bulk_copy(tab_a,              (const char*)g_s_h,              HALF_BYTES, mbar0);
        bulk_copy(tab_a + HALF_BYTES, (const char*)g_s_h + HALF_BYTES, HALF_BYTES, mbar1);
    }

    int gtid = blockIdx.x * EBLK + tid;
    int stride = gridDim.x * EBLK;

    // Index loads in flight while the s-halves fly.
    int si[EPT], di[EPT];
    #pragma unroll
    for (int k = 0; k < EPT; k++) {
        int e = gtid + k * stride;
        bool ok = e < n_edges;
        si[k] = ok ? __ldcs(src + e) : 0;
        di[k] = ok ? __ldcs(dst + e) : 0;
    }

    float part[EPT];
    // s_lo ready: gather low-half src projections.
    mbar_wait(mbar0, 0);
    #pragma unroll
    for (int k = 0; k < EPT; k++)
        if (si[k] < HALF_NODES) part[k] = __half2float(tab[si[k]]);
    // s_hi ready: gather the rest.
    mbar_wait(mbar1, 0);
    #pragma unroll
    for (int k = 0; k < EPT; k++)
        if (si[k] >= HALF_NODES) part[k] = __half2float(tab[si[k]]);

    // All s-reads done before the buffer is overwritten.
    __syncthreads();
    if (tid == 0) {
        asm volatile("fence.proxy.async.shared::cta;" ::: "memory");
        bulk_copy(tab_a,              (const char*)g_d_h,              HALF_BYTES, mbar0);
        bulk_copy(tab_a + HALF_BYTES, (const char*)g_d_h + HALF_BYTES, HALF_BYTES, mbar1);
    }

    // d_lo ready: finish low-half dst edges (overlaps the d_hi copy).
    mbar_wait(mbar0, 1);
    #pragma unroll
    for (int k = 0; k < EPT; k++) {
        int e = gtid + k * stride;
        if (e < n_edges && di[k] < HALF_NODES) {
            float logit = part[k] + __half2float(tab[di[k]]);
            __stcs(out + e, sigmoidf_fast(logit));
        }
    }
    // d_hi ready: finish the rest.
    mbar_wait(mbar1, 1);
    #pragma unroll
    for (int k = 0; k < EPT; k++) {
        int e = gtid + k * stride;
        if (e < n_edges && di[k] >= HALF_NODES) {
            float logit = part[k] + __half2float(tab[di[k]]);
            __stcs(out + e, sigmoidf_fast(logit));
        }
    }
}

extern "C" void kernel_launch(void* const* d_in, const int* in_sizes, int n_in,
                              void* d_out, int out_size) {
    const float* x   = (const float*)d_in[0];
    const int*   src = (const int*)d_in[1];
    const int*   dst = (const int*)d_in[2];
    const float* W   = (const float*)d_in[3];
    const float* b   = (const float*)d_in[4];
    float*       out = (float*)d_out;

    int n_nodes = in_sizes[0] / D;
    int n_edges = in_sizes[1];

    // Kernel 1: 8 nodes per warp, 8 warps/block -> 64 nodes/block
    {
        int nodes_per_block = 8 * 8;
        int blocks = (n_nodes + nodes_per_block - 1) / nodes_per_block;
        node_dots_kernel<<<blocks, 256>>>((const float4*)x, W, b, n_nodes);
    }
    // Kernel 2: pipelined table-swap edge scoring (grid ~140, single wave)
    {
        static bool attr_set = false;
        if (!attr_set) {
            cudaFuncSetAttribute(edge_score_swap_kernel,
                                 cudaFuncAttributeMaxDynamicSharedMemorySize,
                                 SMEM_TOTAL);
            attr_set = true;
        }
        long long per_blk = (long long)EBLK * EPT;
        int blocks = (int)((n_edges + per_blk - 1) / per_blk);  // 140 for 1e6
        edge_score_swap_kernel<<<blocks, EBLK, SMEM_TOTAL>>>(src, dst, out, n_edges);
    }
}

// round 16
// speedup vs baseline: 1.2416x; 1.0019x over previous
#include <cuda_runtime.h>
#include <cuda_fp16.h>
#include <cstdint>

#define MAX_NODES 100000
#define D 128
#define EPT 7           // edges per thread (edge kernel)
#define EBLK 1024       // threads per block (edge kernel)

#define TABLE_BYTES (MAX_NODES * 2)            // one fp16 table = 200000 B
#define STAGE_ELEMS (EPT * EBLK)               // 7168 partials per CTA
#define STAGE_BYTES (STAGE_ELEMS * 2)          // 14336 B
#define SMEM_TABLE_OFF 16                      // mbar @0, table @16
#define SMEM_STAGE_OFF (SMEM_TABLE_OFF + TABLE_BYTES)
#define SMEM_TOTAL (SMEM_STAGE_OFF + STAGE_BYTES)   // 214352 B

// Per-node projections, both fp16. Bias folded into d at the node pass.
__device__ __align__(16) __half g_s_h[MAX_NODES];
__device__ __align__(16) __half g_d_h[MAX_NODES];

__device__ __forceinline__ uint32_t smem_u32(const void* p) {
    uint32_t a;
    asm("{ .reg .u64 t; cvta.to.shared.u64 t, %1; cvt.u32.u64 %0, t; }" : "=r"(a) : "l"(p));
    return a;
}

__device__ __forceinline__ float sigmoidf_fast(float z) {
    return 1.0f / (1.0f + __expf(-z));
}

__device__ __forceinline__ void mbar_wait(uint32_t mbar, int parity) {
    asm volatile(
        "{\n\t.reg .pred P;\n\t"
        "W_%=:\n\t"
        "mbarrier.try_wait.parity.acquire.cta.shared::cta.b64 P, [%0], %1, 0x989680;\n\t"
        "@!P bra W_%=;\n\t}"
        :: "r"(mbar), "r"(parity) : "memory");
}

// Kernel 1 (unchanged, ~7.3us): 8 nodes per warp via 8-lane subgroups,
// 2 nodes per thread, all 8 LDG.128 up-front (MLP=8).
__global__ void node_dots_kernel(const float4* __restrict__ x4,
                                 const float* __restrict__ W,
                                 const float* __restrict__ b,
                                 int n_nodes) {
    __shared__ float4 ws4[32];
    __shared__ float4 wd4[32];
    int tid = threadIdx.x;
    if (tid < 32) ws4[tid] = ((const float4*)W)[tid];
    else if (tid < 64) wd4[tid - 32] = ((const float4*)W)[tid - 32 + 32];
    __syncthreads();

    int lane = tid & 31;
    int g    = lane & 7;
    int sub  = lane >> 3;
    int warpId = (blockIdx.x * blockDim.x + tid) >> 5;
    int base = warpId * 8;
    int nodeA = base + sub;
    int nodeB = base + 4 + sub;
    if (nodeA >= n_nodes) return;
    bool hasB = nodeB < n_nodes;

    const float4* rowA = x4 + (size_t)nodeA * 32;
    const float4* rowB = x4 + (size_t)nodeB * 32;

    float4 va[4], vb[4];
    #pragma unroll
    for (int it = 0; it < 4; it++) va[it] = rowA[it * 8 + g];
    #pragma unroll
    for (int it = 0; it < 4; it++)
        vb[it] = hasB ? rowB[it * 8 + g] : make_float4(0.f, 0.f, 0.f, 0.f);

    float sA = 0.f, dA = 0.f, sB = 0.f, dB = 0.f;
    #pragma unroll
    for (int it = 0; it < 4; it++) {
        float4 a = ws4[it * 8 + g];
        float4 c = wd4[it * 8 + g];
        sA += va[it].x * a.x + va[it].y * a.y + va[it].z * a.z + va[it].w * a.w;
        dA += va[it].x * c.x + va[it].y * c.y + va[it].z * c.z + va[it].w * c.w;
        sB += vb[it].x * a.x + vb[it].y * a.y + vb[it].z * a.z + vb[it].w * a.w;
        dB += vb[it].x * c.x + vb[it].y * c.y + vb[it].z * c.z + vb[it].w * c.w;
    }
    #pragma unroll
    for (int off = 4; off > 0; off >>= 1) {
        sA += __shfl_down_sync(0xFFFFFFFFu, sA, off);
        dA += __shfl_down_sync(0xFFFFFFFFu, dA, off);
        sB += __shfl_down_sync(0xFFFFFFFFu, sB, off);
        dB += __shfl_down_sync(0xFFFFFFFFu, dB, off);
    }
    if (g == 0) {
        float b0 = __ldg(b);
        g_s_h[nodeA] = __float2half(sA);
        g_d_h[nodeA] = __float2half(dA + b0);
        if (hasB) {
            g_s_h[nodeB] = __float2half(sB);
            g_d_h[nodeB] = __float2half(dB + b0);
        }
    }
}

// Kernel 2: CLUSTER-PAIRED table gather. Each CTA of a 2-cluster ingests ONE
// 200KB table (halving the per-SM TMA fill that bounds the swap design).
// rank0 owns the s-table + src indices, rank1 the d-table + dst indices.
// Each rank LDS-gathers its table's parts for BOTH CTAs' edges, pushes the
// peer's partials into peer smem staging with coalesced st.shared::cluster,
// then after one release/acquire cluster barrier combines local part +
// staged part -> sigmoid -> store.
__global__ void __launch_bounds__(EBLK, 1) __cluster_dims__(2, 1, 1)
edge_score_pair_kernel(const int* __restrict__ src,
                       const int* __restrict__ dst,
                       float* __restrict__ out,
                       int n_edges) {
    extern __shared__ char smem_raw[];
    __half* tab   = reinterpret_cast<__half*>(smem_raw + SMEM_TABLE_OFF);
    __half* stage = reinterpret_cast<__half*>(smem_raw + SMEM_STAGE_OFF);
    uint32_t mbar  = smem_u32(smem_raw);
    uint32_t tab_a = smem_u32(tab);

    int tid = threadIdx.x;
    uint32_t rank;
    asm("mov.u32 %0, %%cluster_ctarank;" : "=r"(rank));

    // Per-rank table + index stream (symmetric roles, no divergence)
    const int*    idx  = rank ? dst : src;
    const __half* gtab = rank ? g_d_h : g_s_h;

    if (tid == 0) {
        asm volatile("mbarrier.init.shared.b64 [%0], 1;" :: "r"(mbar) : "memory");
    }
    __syncthreads();
    if (tid == 0) {
        asm volatile("mbarrier.arrive.expect_tx.shared.b64 _, [%0], %1;"
                     :: "r"(mbar), "r"((uint32_t)TABLE_BYTES) : "memory");
        asm volatile(
            "cp.async.bulk.shared::cta.global.mbarrier::complete_tx::bytes [%0], [%1], %2, [%3];"
            :: "r"(tab_a), "l"((const void*)gtab),
               "r"((uint32_t)TABLE_BYTES), "r"(mbar) : "memory");
    }

    int bid      = blockIdx.x;
    int peer_bid = bid ^ 1;
    int stride   = gridDim.x * EBLK;
    int own_g    = bid * EBLK + tid;
    int peer_g   = peer_bid * EBLK + tid;

    // Index loads for both CTAs' edge slots, in flight during the TMA fill.
    int oi[EPT], pi[EPT];
    #pragma unroll
    for (int k = 0; k < EPT; k++) {
        int e1 = own_g + k * stride;
        int e2 = peer_g + k * stride;
        oi[k] = (e1 < n_edges) ? __ldcs(idx + e1) : 0;
        pi[k] = (e2 < n_edges) ? __ldcs(idx + e2) : 0;
    }

    mbar_wait(mbar, 0);

    // Local LDS gathers: own edges' part + peer edges' part.
    __half own_part[EPT], peer_part[EPT];
    #pragma unroll
    for (int k = 0; k < EPT; k++) own_part[k] = tab[oi[k]];
    #pragma unroll
    for (int k = 0; k < EPT; k++) peer_part[k] = tab[pi[k]];

    // Push peer partials into the peer's staging (coalesced 64B/warp-instr).
    uint32_t peer_stage;
    asm("mapa.shared::cluster.u32 %0, %1, %2;"
        : "=r"(peer_stage) : "r"(smem_u32(stage)), "r"(rank ^ 1u));
    #pragma unroll
    for (int k = 0; k < EPT; k++) {
        asm volatile("st.shared::cluster.u16 [%0], %1;"
                     :: "r"(peer_stage + (uint32_t)(k * EBLK + tid) * 2),
                        "h"(__half_as_ushort(peer_part[k])) : "memory");
    }

    // Release pushes / acquire peer's pushes.
    asm volatile("barrier.cluster.arrive.aligned;" ::: "memory");
    asm volatile("barrier.cluster.wait.aligned;" ::: "memory");

    // Combine: local part + staged peer part, sigmoid, coalesced store.
    #pragma unroll
    for (int k = 0; k < EPT; k++) {
        int e = own_g + k * stride;
        if (e < n_edges) {
            float logit = __half2float(own_part[k]) +
                          __half2float(stage[k * EBLK + tid]);
            __stcs(out + e, sigmoidf_fast(logit));
        }
    }
}

extern "C" void kernel_launch(void* const* d_in, const int* in_sizes, int n_in,
                              void* d_out, int out_size) {
    const float* x   = (const float*)d_in[0];
    const int*   src = (const int*)d_in[1];
    const int*   dst = (const int*)d_in[2];
    const float* W   = (const float*)d_in[3];
    const float* b   = (const float*)d_in[4];
    float*       out = (float*)d_out;

    int n_nodes = in_sizes[0] / D;
    int n_edges = in_sizes[1];

    // Kernel 1: 8 nodes per warp, 8 warps/block -> 64 nodes/block
    {
        int nodes_per_block = 8 * 8;
        int blocks = (n_nodes + nodes_per_block - 1) / nodes_per_block;
        node_dots_kernel<<<blocks, 256>>>((const float4*)x, W, b, n_nodes);
    }
    // Kernel 2: cluster-paired edge scoring (grid 140 = 70 clusters)
    {
        static bool attr_set = false;
        if (!attr_set) {
            cudaFuncSetAttribute(edge_score_pair_kernel,
                                 cudaFuncAttributeMaxDynamicSharedMemorySize,
                                 SMEM_TOTAL);
            attr_set = true;
        }
        long long per_blk = (long long)EBLK * EPT;
        int blocks = (int)((n_edges + per_blk - 1) / per_blk);  // 140 for 1e6
        blocks = (blocks + 1) & ~1;                             // even for cluster 2
        edge_score_pair_kernel<<<blocks, EBLK, SMEM_TOTAL>>>(src, dst, out, n_edges);
    }
}